// round 7
// baseline (speedup 1.0000x reference)
#include <cuda_runtime.h>
#include <math.h>

#define NUM_L1 16
#define NUM_L2 8
#define IN_C   30             // 120 floats = 30 float4 chunks
#define N_VD   120
#define N_TD   28
#define EPS_N  1e-6f
#define WPB    8

// output float offsets
#define O_VN   32             // norms (vec then tens, 24 floats, contiguous)
#define O_VD   56
#define O_TD   176

__global__ __launch_bounds__(32 * WPB)
void invariant_extractor_kernel(const float4* __restrict__ h4,
                                float* __restrict__ out,
                                int n_atoms) {
    __shared__ float4 s_in4[WPB][22];          // input chunks 8..29 (vec+tens region)
    __shared__ float4 s_v  [WPB][NUM_L1];      // normalized vecs (padded to float4)
    __shared__ float4 s_t  [WPB][NUM_L2][2];   // normalized tens (padded to 8 floats)
    __shared__ unsigned char s_vp[128];        // vec pair table, p -> (i<<4)|j
    __shared__ unsigned char s_tp[32];         // tens pair table, p -> (i<<3)|j

    const int tid  = threadIdx.x;
    const int w    = tid >> 5;
    const int lane = tid & 31;
    const int atom = blockIdx.x * WPB + w;
    const bool valid = (atom < n_atoms);

    // ---- coalesced vectorized load; scalar chunks 0..7 stay in register ----
    float4 v = make_float4(0.f, 0.f, 0.f, 0.f);
    if (valid && lane < IN_C) {
        v = h4[(size_t)atom * IN_C + lane];
        if (lane >= 8) s_in4[w][lane - 8] = v;
    }

    // ---- build pair tables once per block ----
    if (tid < N_VD + N_TD) {
        int p, n;
        if (tid < N_VD) { p = tid; n = NUM_L1; }
        else            { p = tid - N_VD; n = NUM_L2; }
        int i = 0, rem = p;
        while (rem >= n - 1 - i) { rem -= n - 1 - i; i++; }
        int j = i + 1 + rem;
        if (tid < N_VD) s_vp[tid]        = (unsigned char)((i << 4) | j);
        else            s_tp[tid - N_VD] = (unsigned char)((i << 3) | j);
    }
    __syncthreads();
    if (!valid) return;

    const float* si = (const float*)s_in4[w];   // si[0] == input float 32
    float* orow = out + (size_t)atom * 204;

    // ---- norms: lanes 0..23; normalized comps -> padded smem ----
    if (lane < NUM_L1 + NUM_L2) {
        const bool isv = lane < NUM_L1;
        const int base = isv ? 3 * lane : 48 + 5 * (lane - NUM_L1);
        float c0 = si[base], c1 = si[base + 1], c2 = si[base + 2];
        float c3 = isv ? 0.f : si[base + 3];
        float c4 = isv ? 0.f : si[base + 4];
        float nrm = fmaxf(sqrtf(c0*c0 + c1*c1 + c2*c2 + c3*c3 + c4*c4), EPS_N);
        orow[O_VN + lane] = nrm;                       // out[32..55], coalesced
        float inv = 1.0f / nrm;
        if (isv) {
            s_v[w][lane] = make_float4(c0 * inv, c1 * inv, c2 * inv, 0.f);
        } else {
            const int t = lane - NUM_L1;
            s_t[w][t][0] = make_float4(c0 * inv, c1 * inv, c2 * inv, c3 * inv);
            ((float*)s_t[w][t])[4] = c4 * inv;
        }
    }
    __syncwarp();

    // ---- scalars: direct STG.128 from the load register ----
    if (lane < 8) ((float4*)orow)[lane] = v;           // out[0..31]

    // ---- vector pair dots: pairs p = 4*lane+u; LDS.128 with broadcast dedup ----
    {
        const unsigned int w4 = (lane < 30) ? ((const unsigned int*)s_vp)[lane] : 0u;
        float4 res;
        float* r = (float*)&res;
        #pragma unroll
        for (int u = 0; u < 4; u++) {
            const int ij = (int)((w4 >> (8 * u)) & 0xffu);
            const float4 a = s_v[w][ij >> 4];
            const float4 b = s_v[w][ij & 15];
            float d = a.x * b.x + a.y * b.y + a.z * b.z;
            r[u] = fminf(fmaxf(d, -1.0f), 1.0f);
        }
        if (lane < 30)
            *(float4*)(orow + O_VD + 4 * lane) = res;  // out[56..175], one STG.128
    }

    // ---- tensor pair dots: p = lane (lanes 0..27) ----
    {
        const int ij = (lane < N_TD) ? (int)s_tp[lane] : 0;
        const float* ap = (const float*)s_t[w][ij >> 3];
        const float* bp = (const float*)s_t[w][ij & 7];
        const float4 a0 = *(const float4*)ap;
        const float4 b0 = *(const float4*)bp;
        const float a4 = ap[4], b4 = bp[4];
        float d = a0.x * b0.x + a0.y * b0.y + a0.z * b0.z + a0.w * b0.w + a4 * b4;
        if (lane < N_TD)
            orow[O_TD + lane] = fminf(fmaxf(d, -1.0f), 1.0f);  // out[176..203]
    }
}

extern "C" void kernel_launch(void* const* d_in, const int* in_sizes, int n_in,
                              void* d_out, int out_size) {
    const float4* h = (const float4*)d_in[0];
    float* out = (float*)d_out;
    const int n_atoms = in_sizes[0] / 120;

    const int threads = 32 * WPB;
    const int blocks = (n_atoms + WPB - 1) / WPB;
    invariant_extractor_kernel<<<blocks, threads>>>(h, out, n_atoms);
}

// round 8
// speedup vs baseline: 1.6238x; 1.6238x over previous
#include <cuda_runtime.h>
#include <math.h>

#define NUM_L1 16
#define NUM_L2 8
#define IN_C   30             // 120 floats = 30 float4 chunks
#define N_VD   120
#define N_TD   28
#define EPS_N  1e-6f
#define WPB    8

// output float offsets
#define O_VN   32             // norms (vec then tens, 24 floats, contiguous)
#define O_VD   56
#define O_TD   176

// vec pair table: word w packs pairs p=4w..4w+3, byte u = (i<<4)|j of pair p (triu order)
__device__ const unsigned int g_vp4[30] = {
    0x04030201u, 0x08070605u, 0x0C0B0A09u, 0x120F0E0Du,
    0x16151413u, 0x1A191817u, 0x1E1D1C1Bu, 0x2524231Fu,
    0x29282726u, 0x2D2C2B2Au, 0x35342F2Eu, 0x39383736u,
    0x3D3C3B3Au, 0x46453F3Eu, 0x4A494847u, 0x4E4D4C4Bu,
    0x5857564Fu, 0x5C5B5A59u, 0x675F5E5Du, 0x6B6A6968u,
    0x6F6E6D6Cu, 0x7B7A7978u, 0x7F7E7D7Cu, 0x8C8B8A89u,
    0x9A8F8E8Du, 0x9E9D9C9Bu, 0xADACAB9Fu, 0xBDBCAFAEu,
    0xCECDBFBEu, 0xEFDFDECFu
};
// tens pair table: p -> (i<<3)|j
__device__ const unsigned char g_tp[28] = {
    0x01,0x02,0x03,0x04,0x05,0x06,0x07,
    0x0A,0x0B,0x0C,0x0D,0x0E,0x0F,
    0x13,0x14,0x15,0x16,0x17,
    0x1C,0x1D,0x1E,0x1F,
    0x25,0x26,0x27,
    0x2E,0x2F,
    0x37
};

__global__ __launch_bounds__(32 * WPB)
void invariant_extractor_kernel(const float4* __restrict__ h4,
                                float* __restrict__ out,
                                int n_atoms) {
    __shared__ float4 s_in4[WPB][22];          // input chunks 8..29 (vec+tens region)

    const int w    = threadIdx.x >> 5;
    const int lane = threadIdx.x & 31;
    const int atom = blockIdx.x * WPB + w;
    if (atom >= n_atoms) return;               // warp-uniform

    // ---- coalesced vectorized load; scalar chunks 0..7 stay in register ----
    float4 v = make_float4(0.f, 0.f, 0.f, 0.f);
    if (lane < IN_C) {
        v = h4[(size_t)atom * IN_C + lane];
        if (lane >= 8) s_in4[w][lane - 8] = v;
    }

    // ---- pair-table reads (L1-hot static tables; no per-block build) ----
    const unsigned int w4 = (lane < 30) ? g_vp4[lane] : 0u;
    const int tij = (lane < N_TD) ? (int)g_tp[lane] : 0;

    __syncwarp();

    const float* si = (const float*)s_in4[w];   // si[0] == input float 32
    float* orow = out + (size_t)atom * 204;

    // ---- norms: lanes 0..23, components kept in registers ----
    float a0 = 0.f, a1 = 0.f, a2 = 0.f, a3 = 0.f, a4 = 0.f;
    if (lane < NUM_L1 + NUM_L2) {
        const bool isv = lane < NUM_L1;
        const int base = isv ? 3 * lane : 48 + 5 * (lane - NUM_L1);
        float c0 = si[base], c1 = si[base + 1], c2 = si[base + 2];
        float c3 = isv ? 0.f : si[base + 3];
        float c4 = isv ? 0.f : si[base + 4];
        float nrm = fmaxf(sqrtf(c0*c0 + c1*c1 + c2*c2 + c3*c3 + c4*c4), EPS_N);
        orow[O_VN + lane] = nrm;                       // out[32..55], coalesced
        float inv = 1.0f / nrm;
        a0 = c0 * inv; a1 = c1 * inv; a2 = c2 * inv; a3 = c3 * inv; a4 = c4 * inv;
    }
    __syncwarp();

    // ---- scalars: direct STG.128 from the load register ----
    if (lane < 8) ((float4*)orow)[lane] = v;           // out[0..31]

    // ---- vector pair dots: pairs p = 4*lane+u; operands via shfl.idx ----
    {
        float4 res;
        float* r = (float*)&res;
        #pragma unroll
        for (int u = 0; u < 4; u++) {
            const int ij = (int)((w4 >> (8 * u)) & 0xffu);
            const int i = ij >> 4;
            const int j = ij & 15;
            float bx = __shfl_sync(0xffffffffu, a0, i);
            float by = __shfl_sync(0xffffffffu, a1, i);
            float bz = __shfl_sync(0xffffffffu, a2, i);
            float cx = __shfl_sync(0xffffffffu, a0, j);
            float cy = __shfl_sync(0xffffffffu, a1, j);
            float cz = __shfl_sync(0xffffffffu, a2, j);
            float d = bx * cx + by * cy + bz * cz;
            r[u] = fminf(fmaxf(d, -1.0f), 1.0f);
        }
        if (lane < 30)
            *(float4*)(orow + O_VD + 4 * lane) = res;  // out[56..175], one STG.128
    }

    // ---- tensor pair dots: p = lane (lanes 0..27), sources are lanes 16..23 ----
    {
        const int i = NUM_L1 + (tij >> 3);
        const int j = NUM_L1 + (tij & 7);
        float b0 = __shfl_sync(0xffffffffu, a0, i);
        float b1 = __shfl_sync(0xffffffffu, a1, i);
        float b2 = __shfl_sync(0xffffffffu, a2, i);
        float b3 = __shfl_sync(0xffffffffu, a3, i);
        float b4 = __shfl_sync(0xffffffffu, a4, i);
        float c0 = __shfl_sync(0xffffffffu, a0, j);
        float c1 = __shfl_sync(0xffffffffu, a1, j);
        float c2 = __shfl_sync(0xffffffffu, a2, j);
        float c3 = __shfl_sync(0xffffffffu, a3, j);
        float c4 = __shfl_sync(0xffffffffu, a4, j);
        if (lane < N_TD) {
            float d = b0*c0 + b1*c1 + b2*c2 + b3*c3 + b4*c4;
            orow[O_TD + lane] = fminf(fmaxf(d, -1.0f), 1.0f);  // out[176..203]
        }
    }
}

extern "C" void kernel_launch(void* const* d_in, const int* in_sizes, int n_in,
                              void* d_out, int out_size) {
    const float4* h = (const float4*)d_in[0];
    float* out = (float*)d_out;
    const int n_atoms = in_sizes[0] / 120;

    const int threads = 32 * WPB;
    const int blocks = (n_atoms + WPB - 1) / WPB;
    invariant_extractor_kernel<<<blocks, threads>>>(h, out, n_atoms);
}

// round 9
// speedup vs baseline: 1.6364x; 1.0078x over previous
#include <cuda_runtime.h>
#include <math.h>

#define NUM_L1 16
#define NUM_L2 8
#define IN_C   30             // 120 floats = 30 float4 chunks
#define N_VD   120
#define N_TD   28
#define EPS_N  1e-6f
#define WPB    8

// output float offsets
#define O_VN   32             // norms (vec then tens), 24 contiguous floats
#define O_VD   56
#define O_TD   176

// vec pair table: word w packs pairs p=4w..4w+3, byte u = (i<<4)|j (triu order)
__device__ const unsigned int g_vp4[30] = {
    0x04030201u, 0x08070605u, 0x0C0B0A09u, 0x120F0E0Du,
    0x16151413u, 0x1A191817u, 0x1E1D1C1Bu, 0x2524231Fu,
    0x29282726u, 0x2D2C2B2Au, 0x35342F2Eu, 0x39383736u,
    0x3D3C3B3Au, 0x46453F3Eu, 0x4A494847u, 0x4E4D4C4Bu,
    0x5857564Fu, 0x5C5B5A59u, 0x675F5E5Du, 0x6B6A6968u,
    0x6F6E6D6Cu, 0x7B7A7978u, 0x7F7E7D7Cu, 0x8C8B8A89u,
    0x9A8F8E8Du, 0x9E9D9C9Bu, 0xADACAB9Fu, 0xBDBCAFAEu,
    0xCECDBFBEu, 0xEFDFDECFu
};
// tens pair table: p -> (i<<3)|j
__device__ const unsigned char g_tp[28] = {
    0x01,0x02,0x03,0x04,0x05,0x06,0x07,
    0x0A,0x0B,0x0C,0x0D,0x0E,0x0F,
    0x13,0x14,0x15,0x16,0x17,
    0x1C,0x1D,0x1E,0x1F,
    0x25,0x26,0x27,
    0x2E,0x2F,
    0x37
};

__global__ __launch_bounds__(32 * WPB)
void invariant_extractor_kernel(const float4* __restrict__ h4,
                                float* __restrict__ out,
                                int n_atoms) {
    const int lane = threadIdx.x & 31;
    const int atom = blockIdx.x * WPB + (threadIdx.x >> 5);
    if (atom >= n_atoms) return;               // warp-uniform

    // ---- coalesced vectorized load; lane k holds input chunk k in register ----
    float4 v = make_float4(0.f, 0.f, 0.f, 0.f);
    if (lane < IN_C) v = h4[(size_t)atom * IN_C + lane];

    // ---- pair-table reads (L1-hot) ----
    const unsigned int w4 = (lane < IN_C) ? g_vp4[lane] : 0u;
    const int tij = (lane < N_TD) ? (int)g_tp[lane] : 0;

    float* orow = out + (size_t)atom * 204;

    // ---- norm-operand distribution via shfl from load registers ----
    // norm lane n needs floats f0..f0+4 (vec: 3 used) living in chunks c, c+1
    const bool isv = lane < NUM_L1;
    int f0 = isv ? (32 + 3 * lane) : (80 + 5 * (lane - NUM_L1));
    if (lane >= NUM_L1 + NUM_L2) f0 = 32;       // keep shfl srcs in range for idle lanes
    const int c = f0 >> 2;
    const int r = f0 & 3;

    const float g0 = __shfl_sync(0xffffffffu, v.x, c);
    const float g1 = __shfl_sync(0xffffffffu, v.y, c);
    const float g2 = __shfl_sync(0xffffffffu, v.z, c);
    const float g3 = __shfl_sync(0xffffffffu, v.w, c);
    const float h0 = __shfl_sync(0xffffffffu, v.x, c + 1);
    const float h1 = __shfl_sync(0xffffffffu, v.y, c + 1);
    const float h2 = __shfl_sync(0xffffffffu, v.z, c + 1);
    const float h3 = __shfl_sync(0xffffffffu, v.w, c + 1);

    // ---- scalars: direct STG.128 (v dies here) ----
    if (lane < 8) ((float4*)orow)[lane] = v;    // out[0..31]

    // funnel-select components x[r..r+4] of x = {g0..g3,h0..h3}
    const bool b1 = (r & 2) != 0;
    const bool b0 = (r & 1) != 0;
    const float y0 = b1 ? g2 : g0;
    const float y1 = b1 ? g3 : g1;
    const float y2 = b1 ? h0 : g2;
    const float y3 = b1 ? h1 : g3;
    const float y4 = b1 ? h2 : h0;
    const float y5 = b1 ? h3 : h1;
    float c0 = b0 ? y1 : y0;
    float c1 = b0 ? y2 : y1;
    float c2 = b0 ? y3 : y2;
    float c3 = b0 ? y4 : y3;
    float c4 = b0 ? y5 : y4;
    if (isv) { c3 = 0.f; c4 = 0.f; }

    // ---- norms; normalized components stay in registers ----
    const float nrm = fmaxf(sqrtf(c0*c0 + c1*c1 + c2*c2 + c3*c3 + c4*c4), EPS_N);
    if (lane < NUM_L1 + NUM_L2)
        orow[O_VN + lane] = nrm;                // out[32..55], coalesced
    const float inv = 1.0f / nrm;
    const float a0 = c0 * inv, a1 = c1 * inv, a2 = c2 * inv;
    const float a3 = c3 * inv, a4 = c4 * inv;

    // ---- vector pair dots: pairs p = 4*lane+u; operands via shfl.idx ----
    {
        float4 res;
        float* rr = (float*)&res;
        #pragma unroll
        for (int u = 0; u < 4; u++) {
            const int ij = (int)((w4 >> (8 * u)) & 0xffu);
            const int i = ij >> 4;
            const int j = ij & 15;
            float bx = __shfl_sync(0xffffffffu, a0, i);
            float by = __shfl_sync(0xffffffffu, a1, i);
            float bz = __shfl_sync(0xffffffffu, a2, i);
            float cx = __shfl_sync(0xffffffffu, a0, j);
            float cy = __shfl_sync(0xffffffffu, a1, j);
            float cz = __shfl_sync(0xffffffffu, a2, j);
            float d = bx * cx + by * cy + bz * cz;
            rr[u] = fminf(fmaxf(d, -1.0f), 1.0f);
        }
        if (lane < 30)
            *(float4*)(orow + O_VD + 4 * lane) = res;   // out[56..175], one STG.128
    }

    // ---- tensor pair dots: p = lane (lanes 0..27), sources lanes 16..23 ----
    {
        const int i = NUM_L1 + (tij >> 3);
        const int j = NUM_L1 + (tij & 7);
        float b0s = __shfl_sync(0xffffffffu, a0, i);
        float b1s = __shfl_sync(0xffffffffu, a1, i);
        float b2s = __shfl_sync(0xffffffffu, a2, i);
        float b3s = __shfl_sync(0xffffffffu, a3, i);
        float b4s = __shfl_sync(0xffffffffu, a4, i);
        float c0s = __shfl_sync(0xffffffffu, a0, j);
        float c1s = __shfl_sync(0xffffffffu, a1, j);
        float c2s = __shfl_sync(0xffffffffu, a2, j);
        float c3s = __shfl_sync(0xffffffffu, a3, j);
        float c4s = __shfl_sync(0xffffffffu, a4, j);
        if (lane < N_TD) {
            float d = b0s*c0s + b1s*c1s + b2s*c2s + b3s*c3s + b4s*c4s;
            orow[O_TD + lane] = fminf(fmaxf(d, -1.0f), 1.0f);  // out[176..203]
        }
    }
}

extern "C" void kernel_launch(void* const* d_in, const int* in_sizes, int n_in,
                              void* d_out, int out_size) {
    const float4* h = (const float4*)d_in[0];
    float* out = (float*)d_out;
    const int n_atoms = in_sizes[0] / 120;

    const int threads = 32 * WPB;
    const int blocks = (n_atoms + WPB - 1) / WPB;
    invariant_extractor_kernel<<<blocks, threads>>>(h, out, n_atoms);
}

// round 10
// speedup vs baseline: 1.6763x; 1.0243x over previous
#include <cuda_runtime.h>
#include <cuda_fp16.h>
#include <math.h>

#define NUM_L1 16
#define NUM_L2 8
#define IN_C   30             // 120 floats = 30 float4 chunks
#define N_VD   120
#define N_TD   28
#define EPS_N  1e-6f
#define WPB    8

// output float offsets
#define O_VN   32             // norms (vec then tens), 24 contiguous floats
#define O_VD   56
#define O_TD   176

// vec pair table: word w packs pairs p=4w..4w+3, byte u = (i<<4)|j (triu order)
__device__ const unsigned int g_vp4[30] = {
    0x04030201u, 0x08070605u, 0x0C0B0A09u, 0x120F0E0Du,
    0x16151413u, 0x1A191817u, 0x1E1D1C1Bu, 0x2524231Fu,
    0x29282726u, 0x2D2C2B2Au, 0x35342F2Eu, 0x39383736u,
    0x3D3C3B3Au, 0x46453F3Eu, 0x4A494847u, 0x4E4D4C4Bu,
    0x5857564Fu, 0x5C5B5A59u, 0x675F5E5Du, 0x6B6A6968u,
    0x6F6E6D6Cu, 0x7B7A7978u, 0x7F7E7D7Cu, 0x8C8B8A89u,
    0x9A8F8E8Du, 0x9E9D9C9Bu, 0xADACAB9Fu, 0xBDBCAFAEu,
    0xCECDBFBEu, 0xEFDFDECFu
};
// tens pair table: p -> (i<<3)|j
__device__ const unsigned char g_tp[28] = {
    0x01,0x02,0x03,0x04,0x05,0x06,0x07,
    0x0A,0x0B,0x0C,0x0D,0x0E,0x0F,
    0x13,0x14,0x15,0x16,0x17,
    0x1C,0x1D,0x1E,0x1F,
    0x25,0x26,0x27,
    0x2E,0x2F,
    0x37
};

__global__ __launch_bounds__(32 * WPB)
void invariant_extractor_kernel(const float4* __restrict__ h4,
                                float* __restrict__ out,
                                int n_atoms) {
    const int lane = threadIdx.x & 31;
    const int atom = blockIdx.x * WPB + (threadIdx.x >> 5);
    if (atom >= n_atoms) return;               // warp-uniform

    // ---- coalesced vectorized load; lane k holds input chunk k in register ----
    float4 v = make_float4(0.f, 0.f, 0.f, 0.f);
    if (lane < IN_C) v = h4[(size_t)atom * IN_C + lane];

    // ---- pair-table reads (L1-hot) ----
    const unsigned int w4 = (lane < IN_C) ? g_vp4[lane] : 0u;
    const int tij = (lane < N_TD) ? (int)g_tp[lane] : 0;

    float* orow = out + (size_t)atom * 204;

    // ---- norm-operand distribution via shfl from load registers ----
    const bool isv = lane < NUM_L1;
    int f0 = isv ? (32 + 3 * lane) : (80 + 5 * (lane - NUM_L1));
    if (lane >= NUM_L1 + NUM_L2) f0 = 32;       // safe srcs for idle lanes
    const int c = f0 >> 2;
    const int r = f0 & 3;

    const float g0 = __shfl_sync(0xffffffffu, v.x, c);
    const float g1 = __shfl_sync(0xffffffffu, v.y, c);
    const float g2 = __shfl_sync(0xffffffffu, v.z, c);
    const float g3 = __shfl_sync(0xffffffffu, v.w, c);
    const float h0 = __shfl_sync(0xffffffffu, v.x, c + 1);
    const float h1 = __shfl_sync(0xffffffffu, v.y, c + 1);
    const float h2 = __shfl_sync(0xffffffffu, v.z, c + 1);
    const float h3 = __shfl_sync(0xffffffffu, v.w, c + 1);

    // ---- scalars: direct STG.128 (v no longer needed as shfl src) ----
    if (lane < 8) ((float4*)orow)[lane] = v;    // out[0..31]

    // funnel-select components x[r..r+4] of x = {g0..g3,h0..h3}
    const bool b1 = (r & 2) != 0;
    const bool b0 = (r & 1) != 0;
    const float y0 = b1 ? g2 : g0;
    const float y1 = b1 ? g3 : g1;
    const float y2 = b1 ? h0 : g2;
    const float y3 = b1 ? h1 : g3;
    const float y4 = b1 ? h2 : h0;
    const float y5 = b1 ? h3 : h1;
    float c0 = b0 ? y1 : y0;
    float c1 = b0 ? y2 : y1;
    float c2 = b0 ? y3 : y2;
    float c3 = b0 ? y4 : y3;
    float c4 = b0 ? y5 : y4;
    if (isv) { c3 = 0.f; c4 = 0.f; }

    // ---- norms (exact fp32); normalized components in registers ----
    const float nrm = fmaxf(sqrtf(c0*c0 + c1*c1 + c2*c2 + c3*c3 + c4*c4), EPS_N);
    if (lane < NUM_L1 + NUM_L2)
        orow[O_VN + lane] = nrm;                // out[32..55], coalesced
    const float inv = 1.0f / nrm;
    const float a0 = c0 * inv, a1 = c1 * inv, a2 = c2 * inv;
    const float a3 = c3 * inv, a4 = c4 * inv;

    // ---- pack normalized comps for cheap transport (fp16x2; |a|<=1) ----
    __half2 p01 = __floats2half2_rn(a0, a1);
    __half2 p23 = __floats2half2_rn(a2, a3);
    const unsigned int u01 = *(const unsigned int*)&p01;
    const unsigned int u23 = *(const unsigned int*)&p23;

    // ---- vector pair dots: pairs p = 4*lane+u; 4 shfl per pair (was 6) ----
    {
        float4 res;
        float* rr = (float*)&res;
        #pragma unroll
        for (int u = 0; u < 4; u++) {
            const int ij = (int)((w4 >> (8 * u)) & 0xffu);
            const int i = ij >> 4;
            const int j = ij & 15;
            unsigned int qi01 = __shfl_sync(0xffffffffu, u01, i);
            unsigned int qi23 = __shfl_sync(0xffffffffu, u23, i);
            unsigned int qj01 = __shfl_sync(0xffffffffu, u01, j);
            unsigned int qj23 = __shfl_sync(0xffffffffu, u23, j);
            const __half2 i01 = *(const __half2*)&qi01;
            const __half2 i23 = *(const __half2*)&qi23;
            const __half2 j01 = *(const __half2*)&qj01;
            const __half2 j23 = *(const __half2*)&qj23;
            float d = __low2float(i01)  * __low2float(j01)
                    + __high2float(i01) * __high2float(j01)
                    + __low2float(i23)  * __low2float(j23);
            rr[u] = fminf(fmaxf(d, -1.0f), 1.0f);
        }
        if (lane < 30)
            *(float4*)(orow + O_VD + 4 * lane) = res;   // out[56..175], one STG.128
    }

    // ---- tensor pair dots: p = lane (0..27); 6 shfl per pair (was 10) ----
    {
        const int i = NUM_L1 + (tij >> 3);
        const int j = NUM_L1 + (tij & 7);
        unsigned int qi01 = __shfl_sync(0xffffffffu, u01, i);
        unsigned int qi23 = __shfl_sync(0xffffffffu, u23, i);
        float        qi4  = __shfl_sync(0xffffffffu, a4,  i);
        unsigned int qj01 = __shfl_sync(0xffffffffu, u01, j);
        unsigned int qj23 = __shfl_sync(0xffffffffu, u23, j);
        float        qj4  = __shfl_sync(0xffffffffu, a4,  j);
        const __half2 i01 = *(const __half2*)&qi01;
        const __half2 i23 = *(const __half2*)&qi23;
        const __half2 j01 = *(const __half2*)&qj01;
        const __half2 j23 = *(const __half2*)&qj23;
        if (lane < N_TD) {
            float d = __low2float(i01)  * __low2float(j01)
                    + __high2float(i01) * __high2float(j01)
                    + __low2float(i23)  * __low2float(j23)
                    + __high2float(i23) * __high2float(j23)
                    + qi4 * qj4;
            orow[O_TD + lane] = fminf(fmaxf(d, -1.0f), 1.0f);  // out[176..203]
        }
    }
}

extern "C" void kernel_launch(void* const* d_in, const int* in_sizes, int n_in,
                              void* d_out, int out_size) {
    const float4* h = (const float4*)d_in[0];
    float* out = (float*)d_out;
    const int n_atoms = in_sizes[0] / 120;

    const int threads = 32 * WPB;
    const int blocks = (n_atoms + WPB - 1) / WPB;
    invariant_extractor_kernel<<<blocks, threads>>>(h, out, n_atoms);
}

// round 11
// speedup vs baseline: 1.7730x; 1.0577x over previous
#include <cuda_runtime.h>
#include <cuda_fp16.h>
#include <math.h>

#define NUM_L1 16
#define NUM_L2 8
#define IN_C   30             // 120 floats = 30 float4 chunks
#define N_VD   120
#define N_TD   28
#define EPS_N  1e-6f
#define WPB    8

// output float offsets
#define O_VN   32             // norms (vec then tens), 24 contiguous floats
#define O_VD   56
#define O_TD   176

// vec pair table: word w packs pairs p=4w..4w+3, byte u = (i<<4)|j (triu order)
__device__ const unsigned int g_vp4[30] = {
    0x04030201u, 0x08070605u, 0x0C0B0A09u, 0x120F0E0Du,
    0x16151413u, 0x1A191817u, 0x1E1D1C1Bu, 0x2524231Fu,
    0x29282726u, 0x2D2C2B2Au, 0x35342F2Eu, 0x39383736u,
    0x3D3C3B3Au, 0x46453F3Eu, 0x4A494847u, 0x4E4D4C4Bu,
    0x5857564Fu, 0x5C5B5A59u, 0x675F5E5Du, 0x6B6A6968u,
    0x6F6E6D6Cu, 0x7B7A7978u, 0x7F7E7D7Cu, 0x8C8B8A89u,
    0x9A8F8E8Du, 0x9E9D9C9Bu, 0xADACAB9Fu, 0xBDBCAFAEu,
    0xCECDBFBEu, 0xEFDFDECFu
};
// tens pair table: p -> (i<<3)|j
__device__ const unsigned char g_tp[28] = {
    0x01,0x02,0x03,0x04,0x05,0x06,0x07,
    0x0A,0x0B,0x0C,0x0D,0x0E,0x0F,
    0x13,0x14,0x15,0x16,0x17,
    0x1C,0x1D,0x1E,0x1F,
    0x25,0x26,0x27,
    0x2E,0x2F,
    0x37
};

__global__ __launch_bounds__(32 * WPB)
void invariant_extractor_kernel(const float4* __restrict__ h4,
                                float* __restrict__ out,
                                int n_atoms) {
    const int lane = threadIdx.x & 31;
    const int atom = blockIdx.x * WPB + (threadIdx.x >> 5);
    if (atom >= n_atoms) return;               // warp-uniform

    // ---- coalesced vectorized load; lane k holds input chunk k in register ----
    float4 v = make_float4(0.f, 0.f, 0.f, 0.f);
    if (lane < IN_C) v = h4[(size_t)atom * IN_C + lane];

    // ---- pair-table reads (L1-hot) ----
    const unsigned int w4 = (lane < IN_C) ? g_vp4[lane] : 0u;
    const int tij = (lane < N_TD) ? (int)g_tp[lane] : 0;

    float* orow = out + (size_t)atom * 204;

    // ---- norm-operand distribution via shfl from load registers ----
    const bool isv = lane < NUM_L1;
    int f0 = isv ? (32 + 3 * lane) : (80 + 5 * (lane - NUM_L1));
    if (lane >= NUM_L1 + NUM_L2) f0 = 32;       // safe srcs for idle lanes
    const int c = f0 >> 2;
    const int r = f0 & 3;

    const float g0 = __shfl_sync(0xffffffffu, v.x, c);
    const float g1 = __shfl_sync(0xffffffffu, v.y, c);
    const float g2 = __shfl_sync(0xffffffffu, v.z, c);
    const float g3 = __shfl_sync(0xffffffffu, v.w, c);
    const float h0 = __shfl_sync(0xffffffffu, v.x, c + 1);
    const float h1 = __shfl_sync(0xffffffffu, v.y, c + 1);
    const float h2 = __shfl_sync(0xffffffffu, v.z, c + 1);
    const float h3 = __shfl_sync(0xffffffffu, v.w, c + 1);

    // ---- scalars: direct STG.128 ----
    if (lane < 8) ((float4*)orow)[lane] = v;    // out[0..31]

    // funnel-select components x[r..r+4] of x = {g0..g3,h0..h3}
    const bool b1 = (r & 2) != 0;
    const bool b0 = (r & 1) != 0;
    const float y0 = b1 ? g2 : g0;
    const float y1 = b1 ? g3 : g1;
    const float y2 = b1 ? h0 : g2;
    const float y3 = b1 ? h1 : g3;
    const float y4 = b1 ? h2 : h0;
    const float y5 = b1 ? h3 : h1;
    float c0 = b0 ? y1 : y0;
    float c1 = b0 ? y2 : y1;
    float c2 = b0 ? y3 : y2;
    float c3 = b0 ? y4 : y3;
    float c4 = b0 ? y5 : y4;
    if (isv) { c3 = 0.f; c4 = 0.f; }

    // ---- norms (exact fp32); normalized components in registers ----
    const float nrm = fmaxf(sqrtf(c0*c0 + c1*c1 + c2*c2 + c3*c3 + c4*c4), EPS_N);
    if (lane < NUM_L1 + NUM_L2)
        orow[O_VN + lane] = nrm;                // out[32..55], coalesced
    const float inv = 1.0f / nrm;
    const float a0 = c0 * inv, a1 = c1 * inv, a2 = c2 * inv;
    const float a3 = c3 * inv, a4 = c4 * inv;

    // ---- pack normalized comps for transport (fp16x2; |a|<=1; a3=0 for vecs) ----
    __half2 p01 = __floats2half2_rn(a0, a1);
    __half2 p23 = __floats2half2_rn(a2, a3);
    const unsigned int u01 = *(const unsigned int*)&p01;
    const unsigned int u23 = *(const unsigned int*)&p23;

    // ---- vector pair dots: pairs p = 4*lane+u; packed half2 arithmetic ----
    {
        float4 res;
        float* rr = (float*)&res;
        #pragma unroll
        for (int u = 0; u < 4; u++) {
            const int ij = (int)((w4 >> (8 * u)) & 0xffu);
            const int i = ij >> 4;
            const int j = ij & 15;
            unsigned int qi01 = __shfl_sync(0xffffffffu, u01, i);
            unsigned int qi23 = __shfl_sync(0xffffffffu, u23, i);
            unsigned int qj01 = __shfl_sync(0xffffffffu, u01, j);
            unsigned int qj23 = __shfl_sync(0xffffffffu, u23, j);
            const __half2 i01 = *(const __half2*)&qi01;
            const __half2 i23 = *(const __half2*)&qi23;
            const __half2 j01 = *(const __half2*)&qj01;
            const __half2 j23 = *(const __half2*)&qj23;
            // acc.lo = a0a0' + a2a2'; acc.hi = a1a1' + 0 (a3 = 0 for vecs)
            const __half2 acc = __hfma2(i23, j23, __hmul2(i01, j01));
            float d = __low2float(acc) + __high2float(acc);
            rr[u] = fminf(fmaxf(d, -1.0f), 1.0f);
        }
        if (lane < 30)
            *(float4*)(orow + O_VD + 4 * lane) = res;   // out[56..175], one STG.128
    }

    // ---- tensor pair dots: p = lane (0..27); packed half2 + fp32 a4 term ----
    {
        const int i = NUM_L1 + (tij >> 3);
        const int j = NUM_L1 + (tij & 7);
        unsigned int qi01 = __shfl_sync(0xffffffffu, u01, i);
        unsigned int qi23 = __shfl_sync(0xffffffffu, u23, i);
        float        qi4  = __shfl_sync(0xffffffffu, a4,  i);
        unsigned int qj01 = __shfl_sync(0xffffffffu, u01, j);
        unsigned int qj23 = __shfl_sync(0xffffffffu, u23, j);
        float        qj4  = __shfl_sync(0xffffffffu, a4,  j);
        const __half2 i01 = *(const __half2*)&qi01;
        const __half2 i23 = *(const __half2*)&qi23;
        const __half2 j01 = *(const __half2*)&qj01;
        const __half2 j23 = *(const __half2*)&qj23;
        if (lane < N_TD) {
            const __half2 acc = __hfma2(i23, j23, __hmul2(i01, j01));
            float d = fmaf(qi4, qj4, __low2float(acc) + __high2float(acc));
            orow[O_TD + lane] = fminf(fmaxf(d, -1.0f), 1.0f);  // out[176..203]
        }
    }
}

extern "C" void kernel_launch(void* const* d_in, const int* in_sizes, int n_in,
                              void* d_out, int out_size) {
    const float4* h = (const float4*)d_in[0];
    float* out = (float*)d_out;
    const int n_atoms = in_sizes[0] / 120;

    const int threads = 32 * WPB;
    const int blocks = (n_atoms + WPB - 1) / WPB;
    invariant_extractor_kernel<<<blocks, threads>>>(h, out, n_atoms);
}

// round 12
// speedup vs baseline: 1.8262x; 1.0300x over previous
#include <cuda_runtime.h>
#include <cuda_fp16.h>
#include <math.h>

#define NUM_L1 16
#define NUM_L2 8
#define IN_C   30             // 120 floats = 30 float4 chunks
#define N_VD   120
#define N_TD   28
#define WPB    8

// output float offsets
#define O_VN   32             // norms (vec then tens), 24 contiguous floats
#define O_VD   56
#define O_TD   176

// vec pair table: word w packs pairs p=4w..4w+3, byte u = (i<<4)|j (triu order)
__device__ const unsigned int g_vp4[30] = {
    0x04030201u, 0x08070605u, 0x0C0B0A09u, 0x120F0E0Du,
    0x16151413u, 0x1A191817u, 0x1E1D1C1Bu, 0x2524231Fu,
    0x29282726u, 0x2D2C2B2Au, 0x35342F2Eu, 0x39383736u,
    0x3D3C3B3Au, 0x46453F3Eu, 0x4A494847u, 0x4E4D4C4Bu,
    0x5857564Fu, 0x5C5B5A59u, 0x675F5E5Du, 0x6B6A6968u,
    0x6F6E6D6Cu, 0x7B7A7978u, 0x7F7E7D7Cu, 0x8C8B8A89u,
    0x9A8F8E8Du, 0x9E9D9C9Bu, 0xADACAB9Fu, 0xBDBCAFAEu,
    0xCECDBFBEu, 0xEFDFDECFu
};
// tens pair table: p -> (i+16) | ((j+16)<<8)  (shuffle-ready lane indices)
__device__ const unsigned short g_tp16[28] = {
    0x1110,0x1210,0x1310,0x1410,0x1510,0x1610,0x1710,
    0x1211,0x1311,0x1411,0x1511,0x1611,0x1711,
    0x1312,0x1412,0x1512,0x1612,0x1712,
    0x1413,0x1513,0x1613,0x1713,
    0x1514,0x1614,0x1714,
    0x1615,0x1715,
    0x1716
};

__global__ __launch_bounds__(32 * WPB)
void invariant_extractor_kernel(const float4* __restrict__ h4,
                                float* __restrict__ out,
                                int n_atoms) {
    const int lane = threadIdx.x & 31;
    const int atom = blockIdx.x * WPB + (threadIdx.x >> 5);
    if (atom >= n_atoms) return;               // warp-uniform

    // ---- coalesced vectorized load; lane k holds input chunk k ----
    float4 v = make_float4(0.f, 0.f, 0.f, 0.f);
    unsigned int w4 = 0u;
    if (lane < IN_C) {
        v  = h4[(size_t)atom * IN_C + lane];
        w4 = g_vp4[lane];
    }
    const int tp = (lane < N_TD) ? (int)g_tp16[lane] : 0x1010;  // (16,16) safe default

    float* orow = out + (size_t)atom * 204;

    // ---- pack raw chunk to half2 for cheap norm-operand transport ----
    __half2 hv01 = __floats2half2_rn(v.x, v.y);
    __half2 hv23 = __floats2half2_rn(v.z, v.w);
    const unsigned int r01 = *(const unsigned int*)&hv01;
    const unsigned int r23 = *(const unsigned int*)&hv23;

    // norm lane n needs halves at float offset f0..f0+4, chunks c,c+1
    const bool isv = lane < NUM_L1;
    const int f0 = isv ? (32 + 3 * lane) : (80 + 5 * (lane - NUM_L1));
    const int c  = f0 >> 2;
    const int r  = f0 & 3;

    const unsigned int A = __shfl_sync(0xffffffffu, r01, c);
    const unsigned int B = __shfl_sync(0xffffffffu, r23, c);
    const unsigned int C = __shfl_sync(0xffffffffu, r01, c + 1);
    const unsigned int D = __shfl_sync(0xffffffffu, r23, c + 1);

    // ---- scalars: direct STG.128 from the load register ----
    if (lane < 8) ((float4*)orow)[lane] = v;    // out[0..31]

    // ---- 5-half window select: b1-level SEL + funnel shift by 16*(r&1) ----
    const bool b1 = (r & 2) != 0;
    const unsigned int P = b1 ? B : A;
    const unsigned int Q = b1 ? C : B;
    const unsigned int R = b1 ? D : C;
    const int s = (r & 1) << 4;
    const unsigned int q01 = __funnelshift_r(P, Q, s);
    const unsigned int q23 = __funnelshift_r(Q, R, s);
    const unsigned int q4  = __funnelshift_r(R, R, s);

    const __half2 hc01 = *(const __half2*)&q01;
    const __half2 hc23 = *(const __half2*)&q23;
    float c0 = __low2float(hc01);
    float c1 = __high2float(hc01);
    float c2 = __low2float(hc23);
    float c3 = __high2float(hc23);
    float c4 = __low2float(*(const __half2*)&q4);
    if (isv) { c3 = 0.f; c4 = 0.f; }

    // ---- norm via rsqrt (fast MUFU path); clamp ss so eps semantics hold ----
    float ss = c0*c0 + c1*c1 + c2*c2 + c3*c3 + c4*c4;
    ss = fmaxf(ss, 1e-12f);                     // norm >= 1e-6 == EPS
    const float inv = rsqrtf(ss);
    const float nrm = ss * inv;
    if (lane < NUM_L1 + NUM_L2)
        orow[O_VN + lane] = nrm;                // out[32..55], coalesced

    const float a0 = c0 * inv, a1 = c1 * inv, a2 = c2 * inv;
    const float a3 = c3 * inv, a4 = c4 * inv;

    // ---- pack normalized comps for pair transport (a3 = 0 for vecs) ----
    __half2 p01 = __floats2half2_rn(a0, a1);
    __half2 p23 = __floats2half2_rn(a2, a3);
    const unsigned int u01 = *(const unsigned int*)&p01;
    const unsigned int u23 = *(const unsigned int*)&p23;

    // ---- vector pair dots: pairs p = 4*lane+u; packed half2 arithmetic ----
    {
        float4 res;
        float* rr = (float*)&res;
        #pragma unroll
        for (int u = 0; u < 4; u++) {
            const int ij = (int)((w4 >> (8 * u)) & 0xffu);
            const int i = ij >> 4;
            const int j = ij & 15;
            unsigned int qi01 = __shfl_sync(0xffffffffu, u01, i);
            unsigned int qi23 = __shfl_sync(0xffffffffu, u23, i);
            unsigned int qj01 = __shfl_sync(0xffffffffu, u01, j);
            unsigned int qj23 = __shfl_sync(0xffffffffu, u23, j);
            const __half2 i01 = *(const __half2*)&qi01;
            const __half2 i23 = *(const __half2*)&qi23;
            const __half2 j01 = *(const __half2*)&qj01;
            const __half2 j23 = *(const __half2*)&qj23;
            const __half2 acc = __hfma2(i23, j23, __hmul2(i01, j01));
            float d = __low2float(acc) + __high2float(acc);
            rr[u] = fminf(fmaxf(d, -1.0f), 1.0f);
        }
        if (lane < 30)
            *(float4*)(orow + O_VD + 4 * lane) = res;   // out[56..175], one STG.128
    }

    // ---- tensor pair dots: p = lane (0..27); indices pre-offset to 16..23 ----
    {
        const int i = tp & 0xff;
        const int j = tp >> 8;
        unsigned int qi01 = __shfl_sync(0xffffffffu, u01, i);
        unsigned int qi23 = __shfl_sync(0xffffffffu, u23, i);
        float        qi4  = __shfl_sync(0xffffffffu, a4,  i);
        unsigned int qj01 = __shfl_sync(0xffffffffu, u01, j);
        unsigned int qj23 = __shfl_sync(0xffffffffu, u23, j);
        float        qj4  = __shfl_sync(0xffffffffu, a4,  j);
        const __half2 i01 = *(const __half2*)&qi01;
        const __half2 i23 = *(const __half2*)&qi23;
        const __half2 j01 = *(const __half2*)&qj01;
        const __half2 j23 = *(const __half2*)&qj23;
        if (lane < N_TD) {
            const __half2 acc = __hfma2(i23, j23, __hmul2(i01, j01));
            float d = fmaf(qi4, qj4, __low2float(acc) + __high2float(acc));
            orow[O_TD + lane] = fminf(fmaxf(d, -1.0f), 1.0f);  // out[176..203]
        }
    }
}

extern "C" void kernel_launch(void* const* d_in, const int* in_sizes, int n_in,
                              void* d_out, int out_size) {
    const float4* h = (const float4*)d_in[0];
    float* out = (float*)d_out;
    const int n_atoms = in_sizes[0] / 120;

    const int threads = 32 * WPB;
    const int blocks = (n_atoms + WPB - 1) / WPB;
    invariant_extractor_kernel<<<blocks, threads>>>(h, out, n_atoms);
}

// round 13
// speedup vs baseline: 2.0463x; 1.1205x over previous
#include <cuda_runtime.h>
#include <cuda_fp16.h>
#include <math.h>

#define NUM_L1 16
#define NUM_L2 8
#define IN_C   30             // 120 floats = 30 float4 chunks
#define N_VD   120
#define N_TD   28
#define WPB    8              // warps per block
#define APW    2              // atoms per warp

// output float offsets
#define O_VN   32
#define O_VD   56
#define O_TD   176

// vec pair table: word w packs pairs p=4w..4w+3, byte u = (i<<4)|j (triu order)
__device__ const unsigned int g_vp4[30] = {
    0x04030201u, 0x08070605u, 0x0C0B0A09u, 0x120F0E0Du,
    0x16151413u, 0x1A191817u, 0x1E1D1C1Bu, 0x2524231Fu,
    0x29282726u, 0x2D2C2B2Au, 0x35342F2Eu, 0x39383736u,
    0x3D3C3B3Au, 0x46453F3Eu, 0x4A494847u, 0x4E4D4C4Bu,
    0x5857564Fu, 0x5C5B5A59u, 0x675F5E5Du, 0x6B6A6968u,
    0x6F6E6D6Cu, 0x7B7A7978u, 0x7F7E7D7Cu, 0x8C8B8A89u,
    0x9A8F8E8Du, 0x9E9D9C9Bu, 0xADACAB9Fu, 0xBDBCAFAEu,
    0xCECDBFBEu, 0xEFDFDECFu
};
// tens pair table: p -> (i+16) | ((j+16)<<8)  (shuffle-ready lane indices)
__device__ const unsigned short g_tp16[28] = {
    0x1110,0x1210,0x1310,0x1410,0x1510,0x1610,0x1710,
    0x1211,0x1311,0x1411,0x1511,0x1611,0x1711,
    0x1312,0x1412,0x1512,0x1612,0x1712,
    0x1413,0x1513,0x1613,0x1713,
    0x1514,0x1614,0x1714,
    0x1615,0x1715,
    0x1716
};

struct LaneCtx {
    int c;          // source chunk for norm window
    int s;          // funnel shift (bits)
    bool b1;        // window high-select
    bool isv;       // vec lane?
    int vi0, vj0, vi1, vj1, vi2, vj2, vi3, vj3;   // vec pair lane indices
    int ti, tj;     // tens pair lane indices (pre-offset +16)
};

__device__ __forceinline__ void process_atom(const float4 v, float* __restrict__ orow,
                                             const int lane, const LaneCtx& L) {
    // ---- pack raw chunk for norm-operand transport ----
    __half2 hv01 = __floats2half2_rn(v.x, v.y);
    __half2 hv23 = __floats2half2_rn(v.z, v.w);
    const unsigned int r01 = *(const unsigned int*)&hv01;
    const unsigned int r23 = *(const unsigned int*)&hv23;

    const unsigned int A = __shfl_sync(0xffffffffu, r01, L.c);
    const unsigned int B = __shfl_sync(0xffffffffu, r23, L.c);
    const unsigned int C = __shfl_sync(0xffffffffu, r01, L.c + 1);
    const unsigned int D = __shfl_sync(0xffffffffu, r23, L.c + 1);

    // ---- scalars: direct STG.128 ----
    if (lane < 8) ((float4*)orow)[lane] = v;

    // ---- 5-half window select ----
    const unsigned int P = L.b1 ? B : A;
    const unsigned int Q = L.b1 ? C : B;
    const unsigned int R = L.b1 ? D : C;
    const unsigned int q01 = __funnelshift_r(P, Q, L.s);
    const unsigned int q23 = __funnelshift_r(Q, R, L.s);
    const unsigned int q4  = __funnelshift_r(R, R, L.s);

    const __half2 hc01 = *(const __half2*)&q01;
    const __half2 hc23 = *(const __half2*)&q23;
    float c0 = __low2float(hc01);
    float c1 = __high2float(hc01);
    float c2 = __low2float(hc23);
    float c3 = __high2float(hc23);
    float c4 = __low2float(*(const __half2*)&q4);
    if (L.isv) { c3 = 0.f; c4 = 0.f; }

    // ---- norm via rsqrt ----
    float ss = c0*c0 + c1*c1 + c2*c2 + c3*c3 + c4*c4;
    ss = fmaxf(ss, 1e-12f);
    const float inv = rsqrtf(ss);
    const float nrm = ss * inv;
    if (lane < NUM_L1 + NUM_L2)
        orow[O_VN + lane] = nrm;

    const float a4 = c4 * inv;
    __half2 p01 = __floats2half2_rn(c0 * inv, c1 * inv);
    __half2 p23 = __floats2half2_rn(c2 * inv, c3 * inv);
    const unsigned int u01 = *(const unsigned int*)&p01;
    const unsigned int u23 = *(const unsigned int*)&p23;

    // ---- vector pair dots: pairs p = 4*lane+u ----
    {
        float4 res;
        float* rr = (float*)&res;
        #pragma unroll
        for (int u = 0; u < 4; u++) {
            const int i = (u == 0) ? L.vi0 : (u == 1) ? L.vi1 : (u == 2) ? L.vi2 : L.vi3;
            const int j = (u == 0) ? L.vj0 : (u == 1) ? L.vj1 : (u == 2) ? L.vj2 : L.vj3;
            unsigned int qi01 = __shfl_sync(0xffffffffu, u01, i);
            unsigned int qi23 = __shfl_sync(0xffffffffu, u23, i);
            unsigned int qj01 = __shfl_sync(0xffffffffu, u01, j);
            unsigned int qj23 = __shfl_sync(0xffffffffu, u23, j);
            const __half2 acc = __hfma2(*(const __half2*)&qi23, *(const __half2*)&qj23,
                                        __hmul2(*(const __half2*)&qi01, *(const __half2*)&qj01));
            float d = __low2float(acc) + __high2float(acc);
            rr[u] = fminf(fmaxf(d, -1.0f), 1.0f);
        }
        if (lane < 30)
            *(float4*)(orow + O_VD + 4 * lane) = res;
    }

    // ---- tensor pair dots: p = lane (0..27) ----
    {
        unsigned int qi01 = __shfl_sync(0xffffffffu, u01, L.ti);
        unsigned int qi23 = __shfl_sync(0xffffffffu, u23, L.ti);
        float        qi4  = __shfl_sync(0xffffffffu, a4,  L.ti);
        unsigned int qj01 = __shfl_sync(0xffffffffu, u01, L.tj);
        unsigned int qj23 = __shfl_sync(0xffffffffu, u23, L.tj);
        float        qj4  = __shfl_sync(0xffffffffu, a4,  L.tj);
        const __half2 acc = __hfma2(*(const __half2*)&qi23, *(const __half2*)&qj23,
                                    __hmul2(*(const __half2*)&qi01, *(const __half2*)&qj01));
        if (lane < N_TD) {
            float d = fmaf(qi4, qj4, __low2float(acc) + __high2float(acc));
            orow[O_TD + lane] = fminf(fmaxf(d, -1.0f), 1.0f);
        }
    }
}

__global__ __launch_bounds__(32 * WPB, 6)
void invariant_extractor_kernel(const float4* __restrict__ h4,
                                float* __restrict__ out,
                                int n_atoms) {
    const int lane = threadIdx.x & 31;
    const int a0 = (blockIdx.x * WPB + (threadIdx.x >> 5)) * APW;
    if (a0 >= n_atoms) return;                  // warp-uniform
    const bool has2 = (a0 + 1) < n_atoms;       // warp-uniform

    // ---- both rows' LDGs issued back-to-back (MLP = 2) ----
    const float4* row0 = h4 + (size_t)a0 * IN_C;
    float4 v0 = make_float4(0.f, 0.f, 0.f, 0.f);
    float4 v1 = make_float4(0.f, 0.f, 0.f, 0.f);
    unsigned int w4 = 0u;
    if (lane < IN_C) {
        v0 = row0[lane];
        if (has2) v1 = row0[IN_C + lane];
        w4 = g_vp4[lane];
    }
    const int tp = (lane < N_TD) ? (int)g_tp16[lane] : 0x1010;

    // ---- atom-invariant lane context (shared by both atoms) ----
    LaneCtx L;
    L.isv = lane < NUM_L1;
    const int f0 = L.isv ? (32 + 3 * lane) : (80 + 5 * (lane - NUM_L1));
    L.c  = f0 >> 2;
    const int r = f0 & 3;
    L.b1 = (r & 2) != 0;
    L.s  = (r & 1) << 4;
    L.vi0 = (int)((w4 >>  4) & 15u);  L.vj0 = (int)( w4        & 15u);
    L.vi1 = (int)((w4 >> 12) & 15u);  L.vj1 = (int)((w4 >>  8) & 15u);
    L.vi2 = (int)((w4 >> 20) & 15u);  L.vj2 = (int)((w4 >> 16) & 15u);
    L.vi3 = (int)( w4 >> 28       );  L.vj3 = (int)((w4 >> 24) & 15u);
    L.ti = tp & 0xff;
    L.tj = tp >> 8;

    float* orow = out + (size_t)a0 * 204;
    process_atom(v0, orow, lane, L);
    if (has2) process_atom(v1, orow + 204, lane, L);
}

extern "C" void kernel_launch(void* const* d_in, const int* in_sizes, int n_in,
                              void* d_out, int out_size) {
    const float4* h = (const float4*)d_in[0];
    float* out = (float*)d_out;
    const int n_atoms = in_sizes[0] / 120;

    const int threads = 32 * WPB;
    const int atoms_per_block = WPB * APW;
    const int blocks = (n_atoms + atoms_per_block - 1) / atoms_per_block;
    invariant_extractor_kernel<<<blocks, threads>>>(h, out, n_atoms);
}